// round 12
// baseline (speedup 1.0000x reference)
#include <cuda_runtime.h>
#include <cuda_bf16.h>
#include <cstdint>

#define N_TRIALS   8
#define T_TOTAL    600
#define N_NEURONS  30000
#define T_USE      500
#define N_SAMPLES  50
#define MAX_COUNT  200
#define N_BINS     16
#define EPS        1e-7f
#define SYNC_COST  10.0f

#define NE          8                 // entry chunks per trial (partials dim)
#define ECAP        4096              // per-trial entry capacity (pow2, bitonic)
#define CHUNK_CAP   512               // >= ECAP/NE
#define SLOT_CAP    32                // max samples per trial (50 draws over 8 => ~13 max)
#define FANO_BLOCKS 100               // (sample, bin-half)

__constant__ int c_bins[N_BINS] = {1,1,2,3,4,6,9,13,18,26,38,55,78,113,162,234};

// Scratch (device globals: allocation is forbidden)
__device__ int          g_entries[N_TRIALS * ECAP];     // sorted keys (id<<6 | slot)
__device__ int          g_ecnt[N_TRIALS];               // entries per trial
__device__ int          g_slotSample[N_TRIALS * 64];    // slot -> sample index
__device__ int          g_nslots[N_TRIALS];             // samples per trial
__device__ float        g_part[NE * N_SAMPLES * T_USE]; // partial gather sums
__device__ float        g_fano[N_BINS * N_SAMPLES];     // per-(bin,sample) fano
__device__ unsigned int g_ticket;                       // last-block ticket (self-resets)

// ---------------------------------------------------------------------------
// Phase 0: per-TRIAL merged entry list. One block per trial (8 x 512 thr).
// All (id, sample) pairs of samples assigned to this trial, sorted by id
// (tie-broken by slot via key packing) -> gather iterates ids in ascending
// order across ALL samples of the trial: shared 128B lines hit in L1, and
// DRAM row activations are amortized (~4.4 entries per 1KB row).
// mask is prefix-form => effective count = sum(mask); ids[0:cnt] active.
// sample_ids arrives as int32 (JAX x64-disabled demotes int64 -> int32).
// ---------------------------------------------------------------------------
__global__ void __launch_bounds__(512)
prep_kernel(const int* __restrict__ trials,
            const int* __restrict__ ids,
            const float* __restrict__ mask)
{
    __shared__ int s_keys[ECAP];          // 16 KB
    __shared__ int s_slotSample[64];
    __shared__ int s_cnt[64];
    __shared__ int s_off[65];
    __shared__ int s_nslots;

    const int T    = blockIdx.x;
    const int tid  = threadIdx.x;
    const int lane = tid & 31;
    const int wrp  = tid >> 5;            // 16 warps

    // deterministic slot order: ascending sample index
    if (tid == 0) {
        int ns = 0;
        for (int s = 0; s < N_SAMPLES; ++s)
            if (trials[s] == T) s_slotSample[ns++] = s;
        s_nslots = ns;
    }
    __syncthreads();
    const int nslots = s_nslots;

    // per-slot effective counts (warp per slot, ballot over mask)
    for (int slot = wrp; slot < nslots; slot += 16) {
        const int s = s_slotSample[slot];
        int cnt = 0;
        #pragma unroll
        for (int c = 0; c < 7; ++c) {              // ceil(200/32)
            const int j = c * 32 + lane;
            const bool a = (j < MAX_COUNT) && (mask[s * MAX_COUNT + j] != 0.0f);
            cnt += __popc(__ballot_sync(0xffffffff, a));
        }
        if (lane == 0) s_cnt[slot] = cnt;
    }
    __syncthreads();

    // prefix offsets (serial over <=SLOT_CAP slots)
    if (tid == 0) {
        int acc = 0;
        for (int slot = 0; slot < nslots; ++slot) { s_off[slot] = acc; acc += s_cnt[slot]; }
        s_off[nslots] = acc;
    }
    __syncthreads();
    const int ntot = s_off[nslots];

    // fill keys (pad with INT_MAX)
    for (int i = tid; i < ECAP; i += 512) s_keys[i] = 0x7FFFFFFF;
    __syncthreads();
    for (int slot = 0; slot < nslots; ++slot) {
        const int s   = s_slotSample[slot];
        const int cnt = s_cnt[slot];
        const int off = s_off[slot];
        for (int j = tid; j < cnt; j += 512)
            s_keys[off + j] = (ids[s * MAX_COUNT + j] << 6) | slot;
    }
    __syncthreads();

    // bitonic sort ascending over ECAP
    for (int k = 2; k <= ECAP; k <<= 1) {
        for (int j = k >> 1; j > 0; j >>= 1) {
            for (int idx = tid; idx < ECAP; idx += 512) {
                const int ixj = idx ^ j;
                if (ixj > idx) {
                    const bool up = ((idx & k) == 0);
                    const int a = s_keys[idx], b = s_keys[ixj];
                    if ((a > b) == up) { s_keys[idx] = b; s_keys[ixj] = a; }
                }
            }
            __syncthreads();
        }
    }

    for (int i = tid; i < ntot; i += 512)
        g_entries[T * ECAP + i] = s_keys[i];
    if (tid < 64) g_slotSample[T * 64 + tid] = s_slotSample[tid];
    if (tid == 0) { g_ecnt[T] = ntot; g_nslots[T] = nslots; }
}

// ---------------------------------------------------------------------------
// Phase 1: merged gather. Block = (trial, t-chunk, entry-chunk); thread owns
// one t. Iterates its chunk's id-sorted entries 8 LDGs at a time, adding each
// value into s_acc[slot][tid] (conflict-free smem). Writes each slot's row to
// g_part[(e*N_SAMPLES + sample)]  -- every (e, sample, t) written exactly once
// (sample belongs to exactly one trial), zeros included.
// ---------------------------------------------------------------------------
__global__ void __launch_bounds__(128)
gather_kernel(const float* __restrict__ spikes)
{
    __shared__ int   s_ekeys[CHUNK_CAP];
    __shared__ int   s_slotSample[64];
    __shared__ float s_acc[SLOT_CAP * 128];   // 16 KB

    const int T   = blockIdx.x;
    const int tc  = blockIdx.y;
    const int e   = blockIdx.z;
    const int tid = threadIdx.x;

    const int n  = g_ecnt[T];
    const int lo = (e * n) / NE;
    const int m  = ((e + 1) * n) / NE - lo;       // <= CHUNK_CAP
    const int nslots = g_nslots[T];

    for (int i = tid; i < m; i += 128)
        s_ekeys[i] = g_entries[T * ECAP + lo + i];
    if (tid < 64) s_slotSample[tid] = g_slotSample[T * 64 + tid];
    for (int i = tid; i < nslots * 128; i += 128)
        s_acc[i] = 0.0f;
    __syncthreads();

    const int t = tc * 128 + tid;
    if (t >= T_USE) return;

    const float* __restrict__ base =
        spikes + (size_t)T * ((size_t)T_TOTAL * N_NEURONS)
               + (size_t)t * N_NEURONS;

    float* const acc = s_acc + tid;               // [slot*128 + tid]
    int j = 0;
    for (; j + 8 <= m; j += 8) {
        int   k0 = s_ekeys[j+0], k1 = s_ekeys[j+1], k2 = s_ekeys[j+2], k3 = s_ekeys[j+3];
        int   k4 = s_ekeys[j+4], k5 = s_ekeys[j+5], k6 = s_ekeys[j+6], k7 = s_ekeys[j+7];
        float v0 = __ldg(base + (k0 >> 6));
        float v1 = __ldg(base + (k1 >> 6));
        float v2 = __ldg(base + (k2 >> 6));
        float v3 = __ldg(base + (k3 >> 6));
        float v4 = __ldg(base + (k4 >> 6));
        float v5 = __ldg(base + (k5 >> 6));
        float v6 = __ldg(base + (k6 >> 6));
        float v7 = __ldg(base + (k7 >> 6));
        acc[(k0 & 63) * 128] += v0;
        acc[(k1 & 63) * 128] += v1;
        acc[(k2 & 63) * 128] += v2;
        acc[(k3 & 63) * 128] += v3;
        acc[(k4 & 63) * 128] += v4;
        acc[(k5 & 63) * 128] += v5;
        acc[(k6 & 63) * 128] += v6;
        acc[(k7 & 63) * 128] += v7;
    }
    for (; j < m; ++j) {
        const int k = s_ekeys[j];
        acc[(k & 63) * 128] += __ldg(base + (k >> 6));
    }

    for (int slot = 0; slot < nslots; ++slot)
        g_part[(e * N_SAMPLES + s_slotSample[slot]) * T_USE + t] = acc[slot * 128];
}

// ---------------------------------------------------------------------------
// Phase 2: block = (sample, bin-half); 100 blocks x 256 threads (unchanged).
// Combine NE partials -> smem row; 8 warps each one bin; ticket-fused final.
// ---------------------------------------------------------------------------
__global__ void __launch_bounds__(256)
fano_kernel(const float* __restrict__ exp_fanos, float* __restrict__ out)
{
    __shared__ float s_row[T_USE];
    __shared__ bool  s_last;

    const int s    = blockIdx.x >> 1;
    const int half = blockIdx.x & 1;
    const int tid  = threadIdx.x;
    const int lane = tid & 31;
    const int wid  = tid >> 5;

    for (int i = tid; i < T_USE; i += 256) {
        float v = 0.0f;
        #pragma unroll
        for (int c = 0; c < NE; ++c)
            v += g_part[(c * N_SAMPLES + s) * T_USE + i];
        s_row[i] = v;
    }
    __syncthreads();

    {
        const int b  = half * 8 + wid;
        const int bs = c_bins[b];
        const int nb = T_USE / bs;

        float sum = 0.0f, sumsq = 0.0f;
        for (int k = lane; k < nb; k += 32) {
            const float* rk = s_row + k * bs;
            float c = 0.0f;
            int u = 0;
            for (; u + 4 <= bs; u += 4) {
                float a0 = rk[u], a1 = rk[u+1], a2 = rk[u+2], a3 = rk[u+3];
                c += (a0 + a1) + (a2 + a3);
            }
            for (; u < bs; ++u) c += rk[u];
            sum   += c;
            sumsq += c * c;
        }
        #pragma unroll
        for (int off = 16; off > 0; off >>= 1) {
            sum   += __shfl_down_sync(0xffffffff, sum,   off);
            sumsq += __shfl_down_sync(0xffffffff, sumsq, off);
        }
        if (lane == 0) {
            const float mean = sum / (float)nb;
            const float var  = sumsq / (float)nb - mean * mean;
            g_fano[b * N_SAMPLES + s] = var / fmaxf(mean, EPS);
        }
    }

    __threadfence();
    __syncthreads();
    if (tid == 0) {
        unsigned int old = atomicAdd(&g_ticket, 1u);
        s_last = (old == FANO_BLOCKS - 1);
        if (s_last) g_ticket = 0;             // reset for next graph replay
    }
    __syncthreads();

    if (s_last && wid == 0) {
        float d2 = 0.0f;
        if (lane < N_BINS) {
            float fsum = 0.0f;
            for (int q = 0; q < N_SAMPLES; ++q)
                fsum += g_fano[lane * N_SAMPLES + q];
            const float fm = fsum / (float)N_SAMPLES;
            const float d  = exp_fanos[lane] - fm;
            d2 = d * d;
        }
        #pragma unroll
        for (int off = 16; off > 0; off >>= 1)
            d2 += __shfl_down_sync(0xffffffff, d2, off);
        if (lane == 0)
            out[0] = SYNC_COST * (d2 / (float)N_BINS);
    }
}

// ---------------------------------------------------------------------------
// Inputs (metadata order):
//   0: spikes float32 [8,600,30000]   1: experimental_fanos_mean float32 [16]
//   2: sample_trials int32 [50]       3: sample_ids int32 [50,200]
//   4: sample_mask float32 [50,200]   out: float32 scalar
// ---------------------------------------------------------------------------
extern "C" void kernel_launch(void* const* d_in, const int* in_sizes, int n_in,
                              void* d_out, int out_size)
{
    const float* spikes = (const float*)d_in[0];
    const float* expf_  = (const float*)d_in[1];
    const int*   trials = (const int*)d_in[2];
    const int*   ids    = (const int*)d_in[3];
    const float* mask   = (const float*)d_in[4];
    float*       out    = (float*)d_out;

    prep_kernel<<<N_TRIALS, 512>>>(trials, ids, mask);
    dim3 grid(N_TRIALS, (T_USE + 127) / 128, NE);
    gather_kernel<<<grid, 128>>>(spikes);
    fano_kernel<<<FANO_BLOCKS, 256>>>(expf_, out);
}

// round 13
// speedup vs baseline: 3.2626x; 3.2626x over previous
#include <cuda_runtime.h>
#include <cuda_bf16.h>

#define N_TRIALS   8
#define T_TOTAL    600
#define N_NEURONS  30000
#define T_USE      500
#define N_SAMPLES  50
#define MAX_COUNT  200
#define N_BINS     16
#define EPS        1e-7f
#define SYNC_COST  10.0f

#define NJ          8                 // per-sample id chunks (dynamic split of [0,cnt))
#define JMAX        32                // >= ceil(MAX_COUNT/NJ) = 25
#define FANO_BLOCKS 100               // (sample, bin-half): 50 x 2

__constant__ int c_bins[N_BINS] = {1,1,2,3,4,6,9,13,18,26,38,55,78,113,162,234};

// Scratch (device globals: allocation is forbidden)
__device__ float        g_part[NJ * N_SAMPLES * T_USE];  // partial gather sums
__device__ float        g_fano[N_BINS * N_SAMPLES];      // per-(bin,sample) fano
__device__ unsigned int g_ticket;                        // last-block ticket (self-resets)

// ---------------------------------------------------------------------------
// Phase 1: gather partial sums (R4 topology -- measured best).
// Block = (sample, t-chunk, j-chunk); thread owns one t; 8-wide unrolled
// scattered LDGs (per-warp outstanding-load budget already saturated at 8).
// mask is prefix-form (arange < count) => effective count = sum(mask), and
// ids[0:cnt] are exactly the active ids (duplicates preserved).
// j-chunks split the ACTIVE range [0,cnt) evenly.
// sample_ids arrives as int32 (JAX x64-disabled demotes int64 -> int32).
// ---------------------------------------------------------------------------
__global__ void __launch_bounds__(128)
gather_kernel(const float* __restrict__ spikes,
              const int*   __restrict__ trials,
              const int*   __restrict__ ids,
              const float* __restrict__ mask)
{
    __shared__ int s_ids[JMAX];
    __shared__ int s_cnt;

    const int s   = blockIdx.x;
    const int jc  = blockIdx.z;
    const int tid = threadIdx.x;

    if (tid == 0) s_cnt = 0;
    __syncthreads();

    int local = 0;
    for (int j = tid; j < MAX_COUNT; j += 128)
        if (mask[s * MAX_COUNT + j] != 0.0f) local++;
    if (local) atomicAdd(&s_cnt, local);
    __syncthreads();

    const int cnt = s_cnt;
    const int lo  = (jc * cnt) / NJ;
    const int m   = ((jc + 1) * cnt) / NJ - lo;   // <= 25
    if (tid < m)
        s_ids[tid] = ids[s * MAX_COUNT + lo + tid];
    __syncthreads();

    const int t = blockIdx.y * 128 + tid;
    if (t >= T_USE) return;

    float acc = 0.0f;
    if (m > 0) {
        const float* __restrict__ base =
            spikes + (size_t)trials[s] * ((size_t)T_TOTAL * N_NEURONS)
                   + (size_t)t * N_NEURONS;
        int j = 0;
        for (; j + 8 <= m; j += 8) {
            float v0 = __ldg(base + s_ids[j + 0]);
            float v1 = __ldg(base + s_ids[j + 1]);
            float v2 = __ldg(base + s_ids[j + 2]);
            float v3 = __ldg(base + s_ids[j + 3]);
            float v4 = __ldg(base + s_ids[j + 4]);
            float v5 = __ldg(base + s_ids[j + 5]);
            float v6 = __ldg(base + s_ids[j + 6]);
            float v7 = __ldg(base + s_ids[j + 7]);
            acc += ((v0 + v1) + (v2 + v3)) + ((v4 + v5) + (v6 + v7));
        }
        for (; j < m; ++j) acc += __ldg(base + s_ids[j]);
    }
    g_part[(jc * N_SAMPLES + s) * T_USE + t] = acc;
}

// ---------------------------------------------------------------------------
// Phase 2 (R7 version -- measured best, 9.4us): block = (sample, bin-half);
// 100 blocks x 256 threads. Combine the sample's NJ partials into a smem row
// (fixed order -> deterministic); 8 warps each compute one bin (single-pass
// sum / sum-of-squares, warp shfl reduce). Last block (ticket) computes
// per-bin means, MSE, scales, writes out, and resets the ticket for the next
// graph replay.
// ---------------------------------------------------------------------------
__global__ void __launch_bounds__(256)
fano_kernel(const float* __restrict__ exp_fanos, float* __restrict__ out)
{
    __shared__ float s_row[T_USE];
    __shared__ bool  s_last;

    const int s    = blockIdx.x >> 1;          // sample
    const int half = blockIdx.x & 1;           // bin half (0: bins 0-7, 1: 8-15)
    const int tid  = threadIdx.x;
    const int lane = tid & 31;
    const int wid  = tid >> 5;

    for (int i = tid; i < T_USE; i += 256) {
        float v = 0.0f;
        #pragma unroll
        for (int c = 0; c < NJ; ++c)
            v += g_part[(c * N_SAMPLES + s) * T_USE + i];
        s_row[i] = v;
    }
    __syncthreads();

    {
        const int b  = half * 8 + wid;
        const int bs = c_bins[b];
        const int nb = T_USE / bs;

        float sum = 0.0f, sumsq = 0.0f;
        for (int k = lane; k < nb; k += 32) {
            const float* rk = s_row + k * bs;
            float c = 0.0f;
            int u = 0;
            for (; u + 4 <= bs; u += 4) {
                float a0 = rk[u], a1 = rk[u+1], a2 = rk[u+2], a3 = rk[u+3];
                c += (a0 + a1) + (a2 + a3);
            }
            for (; u < bs; ++u) c += rk[u];
            sum   += c;
            sumsq += c * c;
        }
        #pragma unroll
        for (int off = 16; off > 0; off >>= 1) {
            sum   += __shfl_down_sync(0xffffffff, sum,   off);
            sumsq += __shfl_down_sync(0xffffffff, sumsq, off);
        }
        if (lane == 0) {
            const float mean = sum / (float)nb;
            const float var  = sumsq / (float)nb - mean * mean;
            g_fano[b * N_SAMPLES + s] = var / fmaxf(mean, EPS);
        }
    }

    // last-block reduction -> scalar loss
    __threadfence();
    __syncthreads();
    if (tid == 0) {
        unsigned int old = atomicAdd(&g_ticket, 1u);
        s_last = (old == FANO_BLOCKS - 1);
        if (s_last) g_ticket = 0;          // reset for next graph replay
    }
    __syncthreads();

    if (s_last && wid == 0) {
        float d2 = 0.0f;
        if (lane < N_BINS) {
            float fsum = 0.0f;
            for (int q = 0; q < N_SAMPLES; ++q)
                fsum += g_fano[lane * N_SAMPLES + q];
            const float fm = fsum / (float)N_SAMPLES;
            const float d  = exp_fanos[lane] - fm;
            d2 = d * d;
        }
        #pragma unroll
        for (int off = 16; off > 0; off >>= 1)
            d2 += __shfl_down_sync(0xffffffff, d2, off);
        if (lane == 0)
            out[0] = SYNC_COST * (d2 / (float)N_BINS);
    }
}

// ---------------------------------------------------------------------------
// Inputs (metadata order):
//   0: spikes float32 [8,600,30000]   1: experimental_fanos_mean float32 [16]
//   2: sample_trials int32 [50]       3: sample_ids int32 [50,200]
//   4: sample_mask float32 [50,200]   out: float32 scalar
// ---------------------------------------------------------------------------
extern "C" void kernel_launch(void* const* d_in, const int* in_sizes, int n_in,
                              void* d_out, int out_size)
{
    const float* spikes = (const float*)d_in[0];
    const float* expf_  = (const float*)d_in[1];
    const int*   trials = (const int*)d_in[2];
    const int*   ids    = (const int*)d_in[3];
    const float* mask   = (const float*)d_in[4];
    float*       out    = (float*)d_out;

    dim3 grid(N_SAMPLES, (T_USE + 127) / 128, NJ);
    gather_kernel<<<grid, 128>>>(spikes, trials, ids, mask);
    fano_kernel<<<FANO_BLOCKS, 256>>>(expf_, out);
}